// round 1
// baseline (speedup 1.0000x reference)
#include <cuda_runtime.h>
#include <cuda_bf16.h>
#include <math.h>
#include <stdint.h>

// DelayAndSum: out[b,t] = (1/S) * sum_s x[b, t+d_s, s], zero past T.
// B=16, T=100000, S=128, d_s = rint(s*sin(0.5235987755982988)/2) in [0,32].
//
// Strategy: per (b, t-tile) CTA. cp.async the tile rows [t0, t0+TT+32) x 128
// sensors into swizzled SMEM (4 commit groups), then warp-cooperative compute:
// one LDS.128 per lane per output (lane l serves sensors 4l..4l+3 from rows
// t+l / t+l+1 per host-computed split mask), bfly-reduce, coalesced store.

#define S_SENS   128
#define TT       384            // outputs per CTA
#define HALO     32             // max delay
#define ROWS     (TT + HALO)    // 416 rows in SMEM
#define NTHREADS 384
#define SMEM_BYTES (ROWS * 32 * 16)  // 416*32 float4 = 212992 B

__device__ __forceinline__ int sw_idx(int row, int c4) {
    return row * 32 + (c4 ^ ((row & 3) << 3));
}

__global__ __launch_bounds__(NTHREADS, 1)
void das_kernel(const float* __restrict__ x, float* __restrict__ out,
                int T, uint4 cmask)
{
    extern __shared__ float4 sm[];
    const int tid = threadIdx.x;
    const int b   = blockIdx.y;
    const int t0  = blockIdx.x * TT;
    const float* __restrict__ xb = x + (size_t)b * (size_t)T * S_SENS;

    // ---- Load: 4 chunks of rows, one cp.async commit group each ----
    // chunk p supports compute phase p (outputs [96p, 96p+96) need rows < 96p+128)
    const int chunk_end[4] = {128, 224, 320, 416};
    int beg = 0;
    #pragma unroll
    for (int p = 0; p < 4; ++p) {
        int cnt = (chunk_end[p] - beg) * 32;      // float4 elements this chunk
        for (int i = tid; i < cnt; i += NTHREADS) {
            int row = beg + (i >> 5);
            int c4  = i & 31;
            int dst = sw_idx(row, c4);
            int gr  = t0 + row;
            if (gr < T) {
                uint32_t sa = (uint32_t)__cvta_generic_to_shared(sm + dst);
                const float4* src =
                    (const float4*)(xb + (size_t)gr * S_SENS) + c4;
                asm volatile("cp.async.cg.shared.global [%0], [%1], 16;"
                             :: "r"(sa), "l"(src));
            } else {
                sm[dst] = make_float4(0.f, 0.f, 0.f, 0.f);
            }
        }
        asm volatile("cp.async.commit_group;");
        beg = chunk_end[p];
    }

    // ---- Compute: warp w handles outputs [w*32, w*32+32), in phase w/3 ----
    const int w = tid >> 5;
    const int l = tid & 31;
    const int start = w * 32;

    uint32_t mword = (l < 8)  ? cmask.x :
                     (l < 16) ? cmask.y :
                     (l < 24) ? cmask.z : cmask.w;
    uint32_t bits = (mword >> ((l & 7) * 4)) & 0xFu;
    const bool b0 = bits & 1u, b1 = bits & 2u, b2 = bits & 4u, b3 = bits & 8u;

    float res = 0.f;
    const int myphase = w / 3;

    #pragma unroll
    for (int p = 0; p < 4; ++p) {
        // wait until chunks 0..p have landed (<= 3-p groups pending)
        asm volatile("cp.async.wait_group %0;" :: "n"(3) : "memory");
        if (p >= 1) asm volatile("cp.async.wait_group %0;" :: "n"(2) : "memory");
        if (p >= 2) asm volatile("cp.async.wait_group %0;" :: "n"(1) : "memory");
        if (p >= 3) asm volatile("cp.async.wait_group %0;" :: "n"(0) : "memory");
        __syncthreads();

        if (myphase == p) {
            float4 cur = sm[sw_idx(start + l, l)];
            #pragma unroll 8
            for (int k = 0; k < 32; ++k) {
                float4 nxt = sm[sw_idx(start + l + k + 1, l)];
                float s0 = b0 ? cur.x : nxt.x;
                float s1 = b1 ? cur.y : nxt.y;
                float s2 = b2 ? cur.z : nxt.z;
                float s3 = b3 ? cur.w : nxt.w;
                float sum = (s0 + s1) + (s2 + s3);
                #pragma unroll
                for (int off = 16; off; off >>= 1)
                    sum += __shfl_xor_sync(0xffffffffu, sum, off);
                if (l == k) res = sum;
                cur = nxt;
            }
        }
    }

    const int tg = t0 + start + l;
    if (tg < T)
        out[(size_t)b * T + tg] = res * (1.0f / 128.0f);
}

extern "C" void kernel_launch(void* const* d_in, const int* in_sizes, int n_in,
                              void* d_out, int out_size)
{
    const float* x = (const float*)d_in[0];
    float* out = (float*)d_out;

    const int T = 100000;
    const int B = out_size / T;   // 16

    // Host-side delay table -> per-chunk split mask.
    // bit j of lane l's nibble set  <=>  d(4l+j) == l  (take from row t+l);
    // clear <=> d == l+1 (take from row t+l+1). Matches numpy's
    // round(s*sin(ANGLE)/2) via glibc sin + rint (round-half-even).
    double q = sin(0.5235987755982988);
    uint32_t cm[4] = {0u, 0u, 0u, 0u};
    for (int l = 0; l < 32; ++l) {
        uint32_t nib = 0u;
        for (int j = 0; j < 4; ++j) {
            int s = 4 * l + j;
            int d = (int)rint((double)s * q / 2.0);
            if (d == l) nib |= (1u << j);
        }
        cm[l >> 3] |= nib << ((l & 7) * 4);
    }
    uint4 cmask = make_uint4(cm[0], cm[1], cm[2], cm[3]);

    static int smem_set = 0;
    if (!smem_set) {
        cudaFuncSetAttribute(das_kernel,
                             cudaFuncAttributeMaxDynamicSharedMemorySize,
                             SMEM_BYTES);
        smem_set = 1;
    }

    dim3 grid((T + TT - 1) / TT, B);   // (261, 16)
    das_kernel<<<grid, NTHREADS, SMEM_BYTES>>>(x, out, T, cmask);
}

// round 4
// speedup vs baseline: 1.0758x; 1.0758x over previous
#include <cuda_runtime.h>
#include <cuda_bf16.h>
#include <math.h>
#include <stdint.h>

// DelayAndSum: out[b,t] = (1/128) * sum_s x[b, t+d_s, s], zero past T.
// d_s = rint(s*sin(0.5235987755982988)/2) in [0,32].
//
// SMEM-free streaming design: one warp per 512-output item. Warp streams
// rows t = o0 .. o0+543; lane m loads float4 (sensors 4m..4m+3) of each row
// (warp = one contiguous 512B row -> perfect coalescing). Per row, lane m
// forms a_m (elems with d==m -> out[t-m]) and c_m (d==m+1 -> out[t-m-1]).
// A 32-slot register ring (lane m owns out index == m mod 32) is fed via two
// shfl.idx; the wrapping lane closes out[t-32] and restarts with a_0.
// Completed outputs are contiguous per 32-row block -> coalesced STG.

#define O_OUT    512
#define NTHREADS 256

__global__ __launch_bounds__(NTHREADS)
void das2_kernel(const float* __restrict__ x, float* __restrict__ out,
                 int T, int itemsPerBatch, int nItems, uint4 cmask)
{
    const int gw = (blockIdx.x * NTHREADS + threadIdx.x) >> 5;
    const int m  = threadIdx.x & 31;
    if (gw >= nItems) return;

    const int b  = gw / itemsPerBatch;
    const int o0 = (gw % itemsPerBatch) * O_OUT;   // multiple of 32

    const float* __restrict__ xb = x + (size_t)b * (size_t)T * 128 + 4 * m;
    float* __restrict__ outb = out + (size_t)b * T;

    // per-lane split mask: bit j set <=> d(4m+j) == m (goes to a), else d==m+1 (c)
    uint32_t mword = (m < 8)  ? cmask.x :
                     (m < 16) ? cmask.y :
                     (m < 24) ? cmask.z : cmask.w;
    uint32_t bits = (mword >> ((m & 7) * 4)) & 0xFu;
    const float f0 = (bits & 1u) ? 1.f : 0.f;
    const float f1 = (bits & 2u) ? 1.f : 0.f;
    const float f2 = (bits & 4u) ? 1.f : 0.f;
    const float f3 = (bits & 8u) ? 1.f : 0.f;

    const bool full = (o0 + O_OUT + 32 <= T);

    float acc = 0.f, fin = 0.f;

    #pragma unroll 1
    for (int blk = 0; blk <= O_OUT / 32; ++blk) {
        const int t_base = o0 + blk * 32;          // multiple of 32

        if (full) {
            #pragma unroll 8
            for (int k = 0; k < 32; ++k) {
                const int t = t_base + k;
                float4 v = *(const float4*)(xb + (size_t)t * 128);
                float tot = (v.x + v.y) + (v.z + v.w);
                float a = fmaf(v.x, f0, fmaf(v.y, f1, fmaf(v.z, f2, v.w * f3)));
                float c = tot - a;
                int r = (k - m) & 31;
                float u1 = __shfl_sync(0xffffffffu, a, r);
                float u2 = __shfl_sync(0xffffffffu, c, (r + 31) & 31);
                bool wrap = (r == 0);
                float closed = acc + u2;
                fin = wrap ? closed : fin;
                acc = wrap ? u1 : acc + (u1 + u2);
            }
        } else {
            #pragma unroll 8
            for (int k = 0; k < 32; ++k) {
                const int t = t_base + k;
                float4 v = make_float4(0.f, 0.f, 0.f, 0.f);
                if (t < T) v = *(const float4*)(xb + (size_t)t * 128);
                float tot = (v.x + v.y) + (v.z + v.w);
                float a = fmaf(v.x, f0, fmaf(v.y, f1, fmaf(v.z, f2, v.w * f3)));
                float c = tot - a;
                int r = (k - m) & 31;
                float u1 = __shfl_sync(0xffffffffu, a, r);
                float u2 = __shfl_sync(0xffffffffu, c, (r + 31) & 31);
                bool wrap = (r == 0);
                float closed = acc + u2;
                fin = wrap ? closed : fin;
                acc = wrap ? u1 : acc + (u1 + u2);
            }
        }

        if (blk > 0) {
            int o = t_base - 32 + m;               // contiguous across lanes
            if (o < T) outb[o] = fin * (1.0f / 128.0f);
        }
    }
}

extern "C" void kernel_launch(void* const* d_in, const int* in_sizes, int n_in,
                              void* d_out, int out_size)
{
    const float* x = (const float*)d_in[0];
    float* out = (float*)d_out;

    const int T = 100000;
    const int B = out_size / T;                    // 16

    // Host-side delay split mask (same libm as numpy's round path).
    double q = sin(0.5235987755982988);
    uint32_t cm[4] = {0u, 0u, 0u, 0u};
    for (int l = 0; l < 32; ++l) {
        uint32_t nib = 0u;
        for (int j = 0; j < 4; ++j) {
            int s = 4 * l + j;
            int d = (int)rint((double)s * q / 2.0);
            if (d == l) nib |= (1u << j);
        }
        cm[l >> 3] |= nib << ((l & 7) * 4);
    }
    uint4 cmask = make_uint4(cm[0], cm[1], cm[2], cm[3]);

    const int itemsPerBatch = (T + O_OUT - 1) / O_OUT;   // 196
    const int nItems = B * itemsPerBatch;                // 3136 warps
    const int nThreadsTotal = nItems * 32;
    const int grid = (nThreadsTotal + NTHREADS - 1) / NTHREADS;  // 392 CTAs

    das2_kernel<<<grid, NTHREADS>>>(x, out, T, itemsPerBatch, nItems, cmask);
}